// round 8
// baseline (speedup 1.0000x reference)
#include <cuda_runtime.h>
#include <cuda_bf16.h>
#include <cstdint>

#define CC 2
#define FF 32
#define HH 1024
#define BB 16
#define SS 2048
#define SF (SS + FF)   // 2080
#define NC 16          // K chunks of 64
#define SRB 144        // smem row bytes (128 data + 16 pad)
#define MATB (128 * SRB)
#define STGB (4 * MATB)             // 73728 per stage (Ahi,Alo,Bhi,Blo)
#define NSTG 3
#define SMEM_TOTAL (NSTG * STGB)    // 221184
#define NT 256

typedef __nv_bfloat16 bf16;

// ------------------------------ device scratch ----------------------------
__device__ bf16 g_hidH[(size_t)BB * SS * HH], g_hidL[(size_t)BB * SS * HH];
__device__ bf16 g_WqTH[(size_t)CC * HH * HH], g_WqTL[(size_t)CC * HH * HH];
__device__ bf16 g_WkTH[(size_t)CC * HH * HH], g_WkTL[(size_t)CC * HH * HH];
__device__ bf16 g_McTH[(size_t)CC * HH * HH], g_McTL[(size_t)CC * HH * HH];
__device__ bf16 g_embPH[(size_t)CC * 128 * HH], g_embPL[(size_t)CC * 128 * HH];  // rows>=32 stay 0
__device__ bf16 g_EPH[(size_t)CC * 128 * HH], g_EPL[(size_t)CC * 128 * HH];
__device__ bf16 g_TH[(size_t)CC * BB * SS * HH], g_TL[(size_t)CC * BB * SS * HH];
__device__ float g_wvs[CC * HH];
__device__ float g_vsum[(size_t)CC * BB * SS];

// ------------------------------ helpers -----------------------------------
__device__ __forceinline__ uint32_t smem_to_u32(const void* p) {
    uint32_t a;
    asm("{ .reg .u64 t; cvta.to.shared.u64 t, %1; cvt.u32.u64 %0, t; }" : "=r"(a) : "l"(p));
    return a;
}
__device__ __forceinline__ void split2(float x, bf16& h, bf16& l) {
    h = __float2bfloat16(x);
    l = __float2bfloat16(x - __bfloat162float(h));
}
__device__ __forceinline__ uint32_t packbf(bf16 a, bf16 b) {
    return (uint32_t)__bfloat16_as_ushort(a) | ((uint32_t)__bfloat16_as_ushort(b) << 16);
}
__device__ __forceinline__ void ldsm4(uint32_t* r, uint32_t addr) {
    asm volatile("ldmatrix.sync.aligned.m8n8.x4.shared.b16 {%0,%1,%2,%3}, [%4];"
                 : "=r"(r[0]), "=r"(r[1]), "=r"(r[2]), "=r"(r[3]) : "r"(addr));
}
__device__ __forceinline__ void mma_bf16(float* c, const uint32_t* a, uint32_t b0, uint32_t b1) {
    asm volatile(
        "mma.sync.aligned.m16n8k16.row.col.f32.bf16.bf16.f32 "
        "{%0,%1,%2,%3},{%4,%5,%6,%7},{%8,%9},{%0,%1,%2,%3};"
        : "+f"(c[0]), "+f"(c[1]), "+f"(c[2]), "+f"(c[3])
        : "r"(a[0]), "r"(a[1]), "r"(a[2]), "r"(a[3]), "r"(b0), "r"(b1));
}
#define CPA(s, g) asm volatile("cp.async.cg.shared.global [%0], [%1], 16;" :: "r"(s), "l"(g))
#define CPA_COMMIT() asm volatile("cp.async.commit_group;" ::: "memory")
#define CPA_WAIT2() asm volatile("cp.async.wait_group 2;" ::: "memory")
#define CPA_WAIT1() asm volatile("cp.async.wait_group 1;" ::: "memory")
#define CPA_WAIT0() asm volatile("cp.async.wait_group 0;" ::: "memory")

// ------------------------------ prep kernels ------------------------------
#define HID_BLOCKS 32768   // (BB*SS*HH/4)/256
__global__ void k_cvt(const float* __restrict__ hidden, const float* __restrict__ emb) {
    int bid = blockIdx.x;
    if (bid < HID_BLOCKS) {
        size_t i = (size_t)bid * 256 + threadIdx.x;
        float4 v = ((const float4*)hidden)[i];
        bf16 h0, l0, h1, l1, h2, l2, h3, l3;
        split2(v.x, h0, l0); split2(v.y, h1, l1); split2(v.z, h2, l2); split2(v.w, h3, l3);
        ((uint32_t*)g_hidH)[2 * i] = packbf(h0, h1);
        ((uint32_t*)g_hidH)[2 * i + 1] = packbf(h2, h3);
        ((uint32_t*)g_hidL)[2 * i] = packbf(l0, l1);
        ((uint32_t*)g_hidL)[2 * i + 1] = packbf(l2, l3);
    } else {
        int i = (bid - HID_BLOCKS) * 256 + threadIdx.x;
        int e = i * 4;
        int c = e / (FF * HH);
        int rem = e - c * FF * HH;
        int f = rem / HH, h = rem - f * HH;
        float4 v = ((const float4*)emb)[i];
        bf16 h0, l0, h1, l1, h2, l2, h3, l3;
        split2(v.x, h0, l0); split2(v.y, h1, l1); split2(v.z, h2, l2); split2(v.w, h3, l3);
        size_t o = ((size_t)c * 128 + f) * HH + h;
        *(uint32_t*)&g_embPH[o] = packbf(h0, h1);
        *(uint32_t*)&g_embPH[o + 2] = packbf(h2, h3);
        *(uint32_t*)&g_embPL[o] = packbf(l0, l1);
        *(uint32_t*)&g_embPL[o + 2] = packbf(l2, l3);
    }
}

__global__ void k_tsplit_both(const float* __restrict__ Wq, const float* __restrict__ Wk) {
    __shared__ float t[32][33];
    int z = blockIdx.z;
    int c = z >> 1, W = z & 1;
    const float* I = (W == 0 ? Wq : Wk) + (size_t)c * HH * HH;
    bf16* OH = (W == 0 ? g_WqTH : g_WkTH) + (size_t)c * HH * HH;
    bf16* OL = (W == 0 ? g_WqTL : g_WkTL) + (size_t)c * HH * HH;
    int x = blockIdx.x * 32 + threadIdx.x;
#pragma unroll
    for (int i = threadIdx.y; i < 32; i += 8)
        t[i][threadIdx.x] = I[(size_t)(blockIdx.y * 32 + i) * HH + x];
    __syncthreads();
    int ox = blockIdx.y * 32 + threadIdx.x;
#pragma unroll
    for (int i = threadIdx.y; i < 32; i += 8) {
        float v = t[threadIdx.x][i];
        bf16 h, l;
        split2(v, h, l);
        size_t o = (size_t)(blockIdx.x * 32 + i) * HH + ox;
        OH[o] = h;
        OL[o] = l;
    }
}

__global__ void k_wvsum(const float* __restrict__ Wv) {
    int c = blockIdx.y;
    int h = blockIdx.x * 256 + threadIdx.x;
    const float* W = Wv + (size_t)c * HH * HH;
    float a = 0.f;
#pragma unroll 8
    for (int o = 0; o < HH; ++o) a += W[(size_t)o * HH + h];
    g_wvs[c * HH + h] = a;
}

__global__ void k_vsum(const float* __restrict__ hidden) {
    int w = (blockIdx.x * blockDim.x + threadIdx.x) >> 5;
    int lane = threadIdx.x & 31;
    if (w >= BB * SS) return;
    const float* hr = hidden + (size_t)w * HH;
    float a0 = 0.f, a1 = 0.f;
#pragma unroll 4
    for (int i = lane; i < HH; i += 32) {
        float hv = hr[i];
        a0 += hv * g_wvs[i];
        a1 += hv * g_wvs[HH + i];
    }
#pragma unroll
    for (int off = 16; off; off >>= 1) {
        a0 += __shfl_down_sync(0xFFFFFFFFu, a0, off);
        a1 += __shfl_down_sync(0xFFFFFFFFu, a1, off);
    }
    if (lane == 0) {
        g_vsum[w] = a0;
        g_vsum[(size_t)BB * SS + w] = a1;
    }
}

// ------------------------------ GEMM core ---------------------------------
// C[128,128] = (Ahi+Alo)[128,K] . (Bhi+Blo)[128,K]^T  via 3 bf16 mma splits.
// 8 warps, warp grid 2(m) x 4(n), warp tile 64x32.
// Fragments fully double-buffered across ka; 3-stage cp.async smem pipeline.
// MODE 0: McT   1: E   2: T   3: main (x vsum -> out)
template <int MODE>
__global__ void __launch_bounds__(NT, 1) k_gemm(float* __restrict__ out) {
    extern __shared__ __align__(128) char smem[];
    const uint32_t sb = smem_to_u32(smem);
    const int tid = threadIdx.x, wid = tid >> 5, lane = tid & 31;
    const int bx = blockIdx.x, by = blockIdx.y, bz = blockIdx.z;

    const bf16 *AH, *AL, *BH, *BL;
    if (MODE == 0) {
        size_t cb = (size_t)bz * HH * HH;
        AH = g_WkTH + cb + (size_t)by * 128 * HH; AL = g_WkTL + cb + (size_t)by * 128 * HH;
        BH = g_WqTH + cb + (size_t)bx * 128 * HH; BL = g_WqTL + cb + (size_t)bx * 128 * HH;
    } else if (MODE == 1) {
        AH = g_embPH + (size_t)bz * 128 * HH; AL = g_embPL + (size_t)bz * 128 * HH;
        size_t cb = (size_t)bz * HH * HH;
        BH = g_WkTH + cb + (size_t)bx * 128 * HH; BL = g_WkTL + cb + (size_t)bx * 128 * HH;
    } else if (MODE == 2) {
        AH = g_hidH + (size_t)by * 128 * HH; AL = g_hidL + (size_t)by * 128 * HH;
        size_t cb = (size_t)bz * HH * HH;
        BH = g_McTH + cb + (size_t)bx * 128 * HH; BL = g_McTL + cb + (size_t)bx * 128 * HH;
    } else {
        int c = bz >> 4, b = bz & 15;
        if (by < 16) {
            size_t ro = ((size_t)c * BB * SS + (size_t)b * SS + (size_t)by * 128) * HH;
            AH = g_TH + ro; AL = g_TL + ro;
        } else {
            AH = g_EPH + (size_t)c * 128 * HH; AL = g_EPL + (size_t)c * 128 * HH;
        }
        size_t bo = ((size_t)b * SS + (size_t)bx * 128) * HH;
        BH = g_hidH + bo; BL = g_hidL + bo;
    }
    const bf16* srcs[4] = {AH, AL, BH, BL};

    // loader mapping: row = tid>>1 (128 rows), half = tid&1 (64B), 4x16B units
    const int lrow = tid >> 1, lhalf = tid & 1;
    const uint32_t sRowOff = (uint32_t)(lrow * SRB + lhalf * 64);
    const size_t gRowOff = (size_t)lrow * HH + lhalf * 32;

    // compute mapping: warp tile 64x32
    const int wm = wid >> 2, wn = wid & 3;
    const uint32_t aOff = (uint32_t)((wm * 64 + (lane & 15)) * SRB + ((lane >> 4) << 4));
    const uint32_t bOff = (uint32_t)((wn * 32 + (lane & 7) + ((lane >> 4) & 1) * 8) * SRB +
                                     (((lane >> 3) & 1) << 4));

    float acc[4][4][4] = {};

    // prologue: chunks 0,1 -> stages 0,1
#pragma unroll
    for (int pc = 0; pc < 2; pc++) {
        uint32_t stg = sb + pc * STGB;
        const int kof = pc * 64;
#pragma unroll
        for (int mi = 0; mi < 4; mi++) {
            uint32_t sa = stg + mi * MATB + sRowOff;
            const bf16* gp = srcs[mi] + gRowOff + kof;
#pragma unroll
            for (int i = 0; i < 4; i++) CPA(sa + i * 16, gp + i * 8);
        }
        CPA_COMMIT();
    }

    int stage = 0;
    for (int ck = 0; ck < NC; ck++) {
        // issue chunk ck+2 into the stage freed at the end of the previous iter
        if (ck + 2 < NC) {
            int s2 = stage + 2; if (s2 >= NSTG) s2 -= NSTG;
            uint32_t stg = sb + s2 * STGB;
            const int kof = (ck + 2) * 64;
#pragma unroll
            for (int mi = 0; mi < 4; mi++) {
                uint32_t sa = stg + mi * MATB + sRowOff;
                const bf16* gp = srcs[mi] + gRowOff + kof;
#pragma unroll
                for (int i = 0; i < 4; i++) CPA(sa + i * 16, gp + i * 8);
            }
            CPA_COMMIT();
            CPA_WAIT2();
        } else if (ck + 1 < NC) {
            CPA_WAIT1();
        } else {
            CPA_WAIT0();
        }
        __syncthreads();

        const uint32_t base = sb + stage * STGB;
        const uint32_t pAH = base + aOff, pAL = base + MATB + aOff;
        const uint32_t pBH = base + 2 * MATB + bOff, pBL = base + 3 * MATB + bOff;

        uint32_t Ah[2][4][4], Al[2][4][4], Bh[2][2][4], Bl[2][2][4];
        // preload ka = 0
#pragma unroll
        for (int m = 0; m < 4; m++) ldsm4(Ah[0][m], pAH + m * (16 * SRB));
#pragma unroll
        for (int nb = 0; nb < 2; nb++) ldsm4(Bh[0][nb], pBH + nb * (16 * SRB));
#pragma unroll
        for (int nb = 0; nb < 2; nb++) ldsm4(Bl[0][nb], pBL + nb * (16 * SRB));
#pragma unroll
        for (int m = 0; m < 4; m++) ldsm4(Al[0][m], pAL + m * (16 * SRB));

#pragma unroll
        for (int ka = 0; ka < 4; ka++) {
            const int cur = ka & 1, nxt = cur ^ 1;
            if (ka < 3) {  // prefetch ka+1 fragments (independent of current MMAs)
                const uint32_t ko = (ka + 1) * 32;
#pragma unroll
                for (int m = 0; m < 4; m++) ldsm4(Ah[nxt][m], pAH + m * (16 * SRB) + ko);
#pragma unroll
                for (int nb = 0; nb < 2; nb++) ldsm4(Bh[nxt][nb], pBH + nb * (16 * SRB) + ko);
#pragma unroll
                for (int nb = 0; nb < 2; nb++) ldsm4(Bl[nxt][nb], pBL + nb * (16 * SRB) + ko);
#pragma unroll
                for (int m = 0; m < 4; m++) ldsm4(Al[nxt][m], pAL + m * (16 * SRB) + ko);
            }
#pragma unroll
            for (int m = 0; m < 4; m++)
#pragma unroll
                for (int n8 = 0; n8 < 4; n8++)
                    mma_bf16(acc[m][n8], Ah[cur][m],
                             Bh[cur][n8 >> 1][(n8 & 1) * 2], Bh[cur][n8 >> 1][(n8 & 1) * 2 + 1]);
#pragma unroll
            for (int m = 0; m < 4; m++)
#pragma unroll
                for (int n8 = 0; n8 < 4; n8++)
                    mma_bf16(acc[m][n8], Ah[cur][m],
                             Bl[cur][n8 >> 1][(n8 & 1) * 2], Bl[cur][n8 >> 1][(n8 & 1) * 2 + 1]);
#pragma unroll
            for (int m = 0; m < 4; m++)
#pragma unroll
                for (int n8 = 0; n8 < 4; n8++)
                    mma_bf16(acc[m][n8], Al[cur][m],
                             Bh[cur][n8 >> 1][(n8 & 1) * 2], Bh[cur][n8 >> 1][(n8 & 1) * 2 + 1]);
        }
        __syncthreads();
        if (++stage == NSTG) stage = 0;
    }

    // ------------------------------ epilogue --------------------------------
    const int rBase = wm * 64 + (lane >> 2);
    const int cBase = wn * 32 + (lane & 3) * 2;
    if (MODE == 3) {
        int c = bz >> 4, b = bz & 15;
        const float* vsp = g_vsum + ((size_t)c * BB + b) * SS + bx * 128;
        float* ob = out + ((size_t)b * CC + c) * SF * SS;
#pragma unroll
        for (int m = 0; m < 4; m++) {
            int r0 = by * 128 + m * 16 + rBase;
#pragma unroll
            for (int n8 = 0; n8 < 4; n8++) {
                int cc = cBase + n8 * 8;
                float2 vs = *(const float2*)(vsp + cc);
                size_t col = (size_t)bx * 128 + cc;
                if (r0 < SF) {
                    float2 o;
                    o.x = acc[m][n8][0] * vs.x;
                    o.y = acc[m][n8][1] * vs.y;
                    *(float2*)(ob + (size_t)r0 * SS + col) = o;
                }
                if (r0 + 8 < SF) {
                    float2 o;
                    o.x = acc[m][n8][2] * vs.x;
                    o.y = acc[m][n8][3] * vs.y;
                    *(float2*)(ob + (size_t)(r0 + 8) * SS + col) = o;
                }
            }
        }
    } else {
        bf16 *OH, *OL;
        size_t rowB;
        if (MODE == 0) {
            OH = g_McTH; OL = g_McTL;
            rowB = (size_t)bz * HH * HH + (size_t)(by * 128) * HH;
        } else if (MODE == 1) {
            OH = g_EPH; OL = g_EPL;
            rowB = (size_t)bz * 128 * HH;
        } else {
            OH = g_TH; OL = g_TL;
            rowB = ((size_t)bz * BB * SS + (size_t)by * 128) * HH;
        }
#pragma unroll
        for (int m = 0; m < 4; m++) {
            int r0 = m * 16 + rBase;
#pragma unroll
            for (int n8 = 0; n8 < 4; n8++) {
                int cc = bx * 128 + cBase + n8 * 8;
                bf16 h0, l0, h1, l1;
                split2(acc[m][n8][0], h0, l0);
                split2(acc[m][n8][1], h1, l1);
                *(uint32_t*)&OH[rowB + (size_t)r0 * HH + cc] = packbf(h0, h1);
                *(uint32_t*)&OL[rowB + (size_t)r0 * HH + cc] = packbf(l0, l1);
                split2(acc[m][n8][2], h0, l0);
                split2(acc[m][n8][3], h1, l1);
                *(uint32_t*)&OH[rowB + (size_t)(r0 + 8) * HH + cc] = packbf(h0, h1);
                *(uint32_t*)&OL[rowB + (size_t)(r0 + 8) * HH + cc] = packbf(l0, l1);
            }
        }
    }
}

// ------------------------------ launch ------------------------------------
extern "C" void kernel_launch(void* const* d_in, const int* in_sizes, int n_in,
                              void* d_out, int out_size) {
    const float* hidden = (const float*)d_in[0];
    const float* emb    = (const float*)d_in[1];
    const float* Wk     = (const float*)d_in[2];
    const float* Wq     = (const float*)d_in[3];
    const float* Wv     = (const float*)d_in[4];
    float* out = (float*)d_out;

    cudaFuncSetAttribute(k_gemm<0>, cudaFuncAttributeMaxDynamicSharedMemorySize, SMEM_TOTAL);
    cudaFuncSetAttribute(k_gemm<1>, cudaFuncAttributeMaxDynamicSharedMemorySize, SMEM_TOTAL);
    cudaFuncSetAttribute(k_gemm<2>, cudaFuncAttributeMaxDynamicSharedMemorySize, SMEM_TOTAL);
    cudaFuncSetAttribute(k_gemm<3>, cudaFuncAttributeMaxDynamicSharedMemorySize, SMEM_TOTAL);

    // launch order chosen so the 4th launch (ncu capture slot) is k_gemm<2>
    k_cvt<<<HID_BLOCKS + 64, 256>>>(hidden, emb);                  // 1
    k_tsplit_both<<<dim3(32, 32, 2 * CC), dim3(32, 8)>>>(Wq, Wk);  // 2
    k_gemm<0><<<dim3(8, 8, CC), NT, SMEM_TOTAL>>>(nullptr);        // 3: McT
    k_gemm<2><<<dim3(8, 256, CC), NT, SMEM_TOTAL>>>(nullptr);      // 4: T  <- ncu
    k_gemm<1><<<dim3(8, 1, CC), NT, SMEM_TOTAL>>>(nullptr);        // 5: E
    k_wvsum<<<dim3(HH / 256, CC), 256>>>(Wv);                      // 6
    k_vsum<<<(BB * SS) / 8, 256>>>(hidden);                        // 7
    k_gemm<3><<<dim3(16, 17, CC * BB), NT, SMEM_TOTAL>>>(out);     // 8: scores
}

// round 9
// speedup vs baseline: 1.0002x; 1.0002x over previous
#include <cuda_runtime.h>
#include <cuda_bf16.h>
#include <cstdint>

#define CC 2
#define FF 32
#define HH 1024
#define BB 16
#define SS 2048
#define SF (SS + FF)   // 2080
#define NC 16          // K chunks of 64
#define SRB 144        // smem row bytes (128 data + 16 pad)
#define MATB (128 * SRB)
#define STGB (4 * MATB)             // 73728 per stage (Ahi,Alo,Bhi,Blo)
#define NSTG 3
#define SMEM_TOTAL (NSTG * STGB)    // 221184
#define NT 256

typedef __nv_bfloat16 bf16;

// ------------------------------ device scratch ----------------------------
__device__ bf16 g_hidH[(size_t)BB * SS * HH], g_hidL[(size_t)BB * SS * HH];
__device__ bf16 g_WqTH[(size_t)CC * HH * HH], g_WqTL[(size_t)CC * HH * HH];
__device__ bf16 g_WkTH[(size_t)CC * HH * HH], g_WkTL[(size_t)CC * HH * HH];
__device__ bf16 g_McTH[(size_t)CC * HH * HH], g_McTL[(size_t)CC * HH * HH];
__device__ bf16 g_embPH[(size_t)CC * 128 * HH], g_embPL[(size_t)CC * 128 * HH];  // rows>=32 stay 0
__device__ bf16 g_EPH[(size_t)CC * 128 * HH], g_EPL[(size_t)CC * 128 * HH];
__device__ bf16 g_TH[(size_t)CC * BB * SS * HH], g_TL[(size_t)CC * BB * SS * HH];
__device__ float g_wvs[CC * HH];
__device__ float g_vsum[(size_t)CC * BB * SS];

// ------------------------------ helpers -----------------------------------
__device__ __forceinline__ uint32_t smem_to_u32(const void* p) {
    uint32_t a;
    asm("{ .reg .u64 t; cvta.to.shared.u64 t, %1; cvt.u32.u64 %0, t; }" : "=r"(a) : "l"(p));
    return a;
}
__device__ __forceinline__ void split2(float x, bf16& h, bf16& l) {
    h = __float2bfloat16(x);
    l = __float2bfloat16(x - __bfloat162float(h));
}
__device__ __forceinline__ uint32_t packbf(bf16 a, bf16 b) {
    return (uint32_t)__bfloat16_as_ushort(a) | ((uint32_t)__bfloat16_as_ushort(b) << 16);
}
__device__ __forceinline__ void ldsm4(uint32_t* r, uint32_t addr) {
    asm volatile("ldmatrix.sync.aligned.m8n8.x4.shared.b16 {%0,%1,%2,%3}, [%4];"
                 : "=r"(r[0]), "=r"(r[1]), "=r"(r[2]), "=r"(r[3]) : "r"(addr));
}
__device__ __forceinline__ void mma_bf16(float* c, const uint32_t* a, uint32_t b0, uint32_t b1) {
    asm volatile(
        "mma.sync.aligned.m16n8k16.row.col.f32.bf16.bf16.f32 "
        "{%0,%1,%2,%3},{%4,%5,%6,%7},{%8,%9},{%0,%1,%2,%3};"
        : "+f"(c[0]), "+f"(c[1]), "+f"(c[2]), "+f"(c[3])
        : "r"(a[0]), "r"(a[1]), "r"(a[2]), "r"(a[3]), "r"(b0), "r"(b1));
}
#define CPA(s, g) asm volatile("cp.async.cg.shared.global [%0], [%1], 16;" :: "r"(s), "l"(g))
#define CPA_COMMIT() asm volatile("cp.async.commit_group;" ::: "memory")
#define CPA_WAIT2() asm volatile("cp.async.wait_group 2;" ::: "memory")
#define CPA_WAIT1() asm volatile("cp.async.wait_group 1;" ::: "memory")
#define CPA_WAIT0() asm volatile("cp.async.wait_group 0;" ::: "memory")

// ------------------------------ prep kernels ------------------------------
#define HID_BLOCKS 32768   // (BB*SS*HH/4)/256
__global__ void k_cvt(const float* __restrict__ hidden, const float* __restrict__ emb) {
    int bid = blockIdx.x;
    if (bid < HID_BLOCKS) {
        size_t i = (size_t)bid * 256 + threadIdx.x;
        float4 v = ((const float4*)hidden)[i];
        bf16 h0, l0, h1, l1, h2, l2, h3, l3;
        split2(v.x, h0, l0); split2(v.y, h1, l1); split2(v.z, h2, l2); split2(v.w, h3, l3);
        ((uint32_t*)g_hidH)[2 * i] = packbf(h0, h1);
        ((uint32_t*)g_hidH)[2 * i + 1] = packbf(h2, h3);
        ((uint32_t*)g_hidL)[2 * i] = packbf(l0, l1);
        ((uint32_t*)g_hidL)[2 * i + 1] = packbf(l2, l3);
    } else {
        int i = (bid - HID_BLOCKS) * 256 + threadIdx.x;
        int e = i * 4;
        int c = e / (FF * HH);
        int rem = e - c * FF * HH;
        int f = rem / HH, h = rem - f * HH;
        float4 v = ((const float4*)emb)[i];
        bf16 h0, l0, h1, l1, h2, l2, h3, l3;
        split2(v.x, h0, l0); split2(v.y, h1, l1); split2(v.z, h2, l2); split2(v.w, h3, l3);
        size_t o = ((size_t)c * 128 + f) * HH + h;
        *(uint32_t*)&g_embPH[o] = packbf(h0, h1);
        *(uint32_t*)&g_embPH[o + 2] = packbf(h2, h3);
        *(uint32_t*)&g_embPL[o] = packbf(l0, l1);
        *(uint32_t*)&g_embPL[o + 2] = packbf(l2, l3);
    }
}

__global__ void k_tsplit_both(const float* __restrict__ Wq, const float* __restrict__ Wk) {
    __shared__ float t[32][33];
    int z = blockIdx.z;
    int c = z >> 1, W = z & 1;
    const float* I = (W == 0 ? Wq : Wk) + (size_t)c * HH * HH;
    bf16* OH = (W == 0 ? g_WqTH : g_WkTH) + (size_t)c * HH * HH;
    bf16* OL = (W == 0 ? g_WqTL : g_WkTL) + (size_t)c * HH * HH;
    int x = blockIdx.x * 32 + threadIdx.x;
#pragma unroll
    for (int i = threadIdx.y; i < 32; i += 8)
        t[i][threadIdx.x] = I[(size_t)(blockIdx.y * 32 + i) * HH + x];
    __syncthreads();
    int ox = blockIdx.y * 32 + threadIdx.x;
#pragma unroll
    for (int i = threadIdx.y; i < 32; i += 8) {
        float v = t[threadIdx.x][i];
        bf16 h, l;
        split2(v, h, l);
        size_t o = (size_t)(blockIdx.x * 32 + i) * HH + ox;
        OH[o] = h;
        OL[o] = l;
    }
}

__global__ void k_wvsum(const float* __restrict__ Wv) {
    int c = blockIdx.y;
    int h = blockIdx.x * 256 + threadIdx.x;
    const float* W = Wv + (size_t)c * HH * HH;
    float a = 0.f;
#pragma unroll 8
    for (int o = 0; o < HH; ++o) a += W[(size_t)o * HH + h];
    g_wvs[c * HH + h] = a;
}

__global__ void k_vsum(const float* __restrict__ hidden) {
    int w = (blockIdx.x * blockDim.x + threadIdx.x) >> 5;
    int lane = threadIdx.x & 31;
    if (w >= BB * SS) return;
    const float* hr = hidden + (size_t)w * HH;
    float a0 = 0.f, a1 = 0.f;
#pragma unroll 4
    for (int i = lane; i < HH; i += 32) {
        float hv = hr[i];
        a0 += hv * g_wvs[i];
        a1 += hv * g_wvs[HH + i];
    }
#pragma unroll
    for (int off = 16; off; off >>= 1) {
        a0 += __shfl_down_sync(0xFFFFFFFFu, a0, off);
        a1 += __shfl_down_sync(0xFFFFFFFFu, a1, off);
    }
    if (lane == 0) {
        g_vsum[w] = a0;
        g_vsum[(size_t)BB * SS + w] = a1;
    }
}

// ------------------------------ GEMM core ---------------------------------
// C[128,128] = (Ahi+Alo)[128,K] . (Bhi+Blo)[128,K]^T  via 3 bf16 mma splits.
// 8 warps, warp grid 2(m) x 4(n), warp tile 64x32.
// Fragments fully double-buffered across ka; 3-stage cp.async smem pipeline.
// MODE 0: McT   1: E   2: T   3: main (x vsum -> out)
template <int MODE>
__global__ void __launch_bounds__(NT, 1) k_gemm(float* __restrict__ out) {
    extern __shared__ __align__(128) char smem[];
    const uint32_t sb = smem_to_u32(smem);
    const int tid = threadIdx.x, wid = tid >> 5, lane = tid & 31;
    const int bx = blockIdx.x, by = blockIdx.y, bz = blockIdx.z;

    const bf16 *AH, *AL, *BH, *BL;
    if (MODE == 0) {
        size_t cb = (size_t)bz * HH * HH;
        AH = g_WkTH + cb + (size_t)by * 128 * HH; AL = g_WkTL + cb + (size_t)by * 128 * HH;
        BH = g_WqTH + cb + (size_t)bx * 128 * HH; BL = g_WqTL + cb + (size_t)bx * 128 * HH;
    } else if (MODE == 1) {
        AH = g_embPH + (size_t)bz * 128 * HH; AL = g_embPL + (size_t)bz * 128 * HH;
        size_t cb = (size_t)bz * HH * HH;
        BH = g_WkTH + cb + (size_t)bx * 128 * HH; BL = g_WkTL + cb + (size_t)bx * 128 * HH;
    } else if (MODE == 2) {
        AH = g_hidH + (size_t)by * 128 * HH; AL = g_hidL + (size_t)by * 128 * HH;
        size_t cb = (size_t)bz * HH * HH;
        BH = g_McTH + cb + (size_t)bx * 128 * HH; BL = g_McTL + cb + (size_t)bx * 128 * HH;
    } else {
        int c = bz >> 4, b = bz & 15;
        if (by < 16) {
            size_t ro = ((size_t)c * BB * SS + (size_t)b * SS + (size_t)by * 128) * HH;
            AH = g_TH + ro; AL = g_TL + ro;
        } else {
            AH = g_EPH + (size_t)c * 128 * HH; AL = g_EPL + (size_t)c * 128 * HH;
        }
        size_t bo = ((size_t)b * SS + (size_t)bx * 128) * HH;
        BH = g_hidH + bo; BL = g_hidL + bo;
    }
    const bf16* srcs[4] = {AH, AL, BH, BL};

    // loader mapping: row = tid>>1 (128 rows), half = tid&1 (64B), 4x16B units
    const int lrow = tid >> 1, lhalf = tid & 1;
    const uint32_t sRowOff = (uint32_t)(lrow * SRB + lhalf * 64);
    const size_t gRowOff = (size_t)lrow * HH + lhalf * 32;

    // compute mapping: warp tile 64x32
    const int wm = wid >> 2, wn = wid & 3;
    const uint32_t aOff = (uint32_t)((wm * 64 + (lane & 15)) * SRB + ((lane >> 4) << 4));
    const uint32_t bOff = (uint32_t)((wn * 32 + (lane & 7) + ((lane >> 4) & 1) * 8) * SRB +
                                     (((lane >> 3) & 1) << 4));

    float acc[4][4][4] = {};

    // prologue: chunks 0,1 -> stages 0,1
#pragma unroll
    for (int pc = 0; pc < 2; pc++) {
        uint32_t stg = sb + pc * STGB;
        const int kof = pc * 64;
#pragma unroll
        for (int mi = 0; mi < 4; mi++) {
            uint32_t sa = stg + mi * MATB + sRowOff;
            const bf16* gp = srcs[mi] + gRowOff + kof;
#pragma unroll
            for (int i = 0; i < 4; i++) CPA(sa + i * 16, gp + i * 8);
        }
        CPA_COMMIT();
    }

    int stage = 0;
    for (int ck = 0; ck < NC; ck++) {
        // issue chunk ck+2 into the stage freed at the end of the previous iter
        if (ck + 2 < NC) {
            int s2 = stage + 2; if (s2 >= NSTG) s2 -= NSTG;
            uint32_t stg = sb + s2 * STGB;
            const int kof = (ck + 2) * 64;
#pragma unroll
            for (int mi = 0; mi < 4; mi++) {
                uint32_t sa = stg + mi * MATB + sRowOff;
                const bf16* gp = srcs[mi] + gRowOff + kof;
#pragma unroll
                for (int i = 0; i < 4; i++) CPA(sa + i * 16, gp + i * 8);
            }
            CPA_COMMIT();
            CPA_WAIT2();
        } else if (ck + 1 < NC) {
            CPA_WAIT1();
        } else {
            CPA_WAIT0();
        }
        __syncthreads();

        const uint32_t base = sb + stage * STGB;
        const uint32_t pAH = base + aOff, pAL = base + MATB + aOff;
        const uint32_t pBH = base + 2 * MATB + bOff, pBL = base + 3 * MATB + bOff;

        uint32_t Ah[2][4][4], Al[2][4][4], Bh[2][2][4], Bl[2][2][4];
        // preload ka = 0
#pragma unroll
        for (int m = 0; m < 4; m++) ldsm4(Ah[0][m], pAH + m * (16 * SRB));
#pragma unroll
        for (int nb = 0; nb < 2; nb++) ldsm4(Bh[0][nb], pBH + nb * (16 * SRB));
#pragma unroll
        for (int nb = 0; nb < 2; nb++) ldsm4(Bl[0][nb], pBL + nb * (16 * SRB));
#pragma unroll
        for (int m = 0; m < 4; m++) ldsm4(Al[0][m], pAL + m * (16 * SRB));

#pragma unroll
        for (int ka = 0; ka < 4; ka++) {
            const int cur = ka & 1, nxt = cur ^ 1;
            if (ka < 3) {  // prefetch ka+1 fragments (independent of current MMAs)
                const uint32_t ko = (ka + 1) * 32;
#pragma unroll
                for (int m = 0; m < 4; m++) ldsm4(Ah[nxt][m], pAH + m * (16 * SRB) + ko);
#pragma unroll
                for (int nb = 0; nb < 2; nb++) ldsm4(Bh[nxt][nb], pBH + nb * (16 * SRB) + ko);
#pragma unroll
                for (int nb = 0; nb < 2; nb++) ldsm4(Bl[nxt][nb], pBL + nb * (16 * SRB) + ko);
#pragma unroll
                for (int m = 0; m < 4; m++) ldsm4(Al[nxt][m], pAL + m * (16 * SRB) + ko);
            }
#pragma unroll
            for (int m = 0; m < 4; m++)
#pragma unroll
                for (int n8 = 0; n8 < 4; n8++)
                    mma_bf16(acc[m][n8], Ah[cur][m],
                             Bh[cur][n8 >> 1][(n8 & 1) * 2], Bh[cur][n8 >> 1][(n8 & 1) * 2 + 1]);
#pragma unroll
            for (int m = 0; m < 4; m++)
#pragma unroll
                for (int n8 = 0; n8 < 4; n8++)
                    mma_bf16(acc[m][n8], Ah[cur][m],
                             Bl[cur][n8 >> 1][(n8 & 1) * 2], Bl[cur][n8 >> 1][(n8 & 1) * 2 + 1]);
#pragma unroll
            for (int m = 0; m < 4; m++)
#pragma unroll
                for (int n8 = 0; n8 < 4; n8++)
                    mma_bf16(acc[m][n8], Al[cur][m],
                             Bh[cur][n8 >> 1][(n8 & 1) * 2], Bh[cur][n8 >> 1][(n8 & 1) * 2 + 1]);
        }
        __syncthreads();
        if (++stage == NSTG) stage = 0;
    }

    // ------------------------------ epilogue --------------------------------
    const int rBase = wm * 64 + (lane >> 2);
    const int cBase = wn * 32 + (lane & 3) * 2;
    if (MODE == 3) {
        int c = bz >> 4, b = bz & 15;
        const float* vsp = g_vsum + ((size_t)c * BB + b) * SS + bx * 128;
        float* ob = out + ((size_t)b * CC + c) * SF * SS;
#pragma unroll
        for (int m = 0; m < 4; m++) {
            int r0 = by * 128 + m * 16 + rBase;
#pragma unroll
            for (int n8 = 0; n8 < 4; n8++) {
                int cc = cBase + n8 * 8;
                float2 vs = *(const float2*)(vsp + cc);
                size_t col = (size_t)bx * 128 + cc;
                if (r0 < SF) {
                    float2 o;
                    o.x = acc[m][n8][0] * vs.x;
                    o.y = acc[m][n8][1] * vs.y;
                    *(float2*)(ob + (size_t)r0 * SS + col) = o;
                }
                if (r0 + 8 < SF) {
                    float2 o;
                    o.x = acc[m][n8][2] * vs.x;
                    o.y = acc[m][n8][3] * vs.y;
                    *(float2*)(ob + (size_t)(r0 + 8) * SS + col) = o;
                }
            }
        }
    } else {
        bf16 *OH, *OL;
        size_t rowB;
        if (MODE == 0) {
            OH = g_McTH; OL = g_McTL;
            rowB = (size_t)bz * HH * HH + (size_t)(by * 128) * HH;
        } else if (MODE == 1) {
            OH = g_EPH; OL = g_EPL;
            rowB = (size_t)bz * 128 * HH;
        } else {
            OH = g_TH; OL = g_TL;
            rowB = ((size_t)bz * BB * SS + (size_t)by * 128) * HH;
        }
#pragma unroll
        for (int m = 0; m < 4; m++) {
            int r0 = m * 16 + rBase;
#pragma unroll
            for (int n8 = 0; n8 < 4; n8++) {
                int cc = bx * 128 + cBase + n8 * 8;
                bf16 h0, l0, h1, l1;
                split2(acc[m][n8][0], h0, l0);
                split2(acc[m][n8][1], h1, l1);
                *(uint32_t*)&OH[rowB + (size_t)r0 * HH + cc] = packbf(h0, h1);
                *(uint32_t*)&OL[rowB + (size_t)r0 * HH + cc] = packbf(l0, l1);
                split2(acc[m][n8][2], h0, l0);
                split2(acc[m][n8][3], h1, l1);
                *(uint32_t*)&OH[rowB + (size_t)(r0 + 8) * HH + cc] = packbf(h0, h1);
                *(uint32_t*)&OL[rowB + (size_t)(r0 + 8) * HH + cc] = packbf(l0, l1);
            }
        }
    }
}

// ------------------------------ launch ------------------------------------
extern "C" void kernel_launch(void* const* d_in, const int* in_sizes, int n_in,
                              void* d_out, int out_size) {
    const float* hidden = (const float*)d_in[0];
    const float* emb    = (const float*)d_in[1];
    const float* Wk     = (const float*)d_in[2];
    const float* Wq     = (const float*)d_in[3];
    const float* Wv     = (const float*)d_in[4];
    float* out = (float*)d_out;

    cudaFuncSetAttribute(k_gemm<0>, cudaFuncAttributeMaxDynamicSharedMemorySize, SMEM_TOTAL);
    cudaFuncSetAttribute(k_gemm<1>, cudaFuncAttributeMaxDynamicSharedMemorySize, SMEM_TOTAL);
    cudaFuncSetAttribute(k_gemm<2>, cudaFuncAttributeMaxDynamicSharedMemorySize, SMEM_TOTAL);
    cudaFuncSetAttribute(k_gemm<3>, cudaFuncAttributeMaxDynamicSharedMemorySize, SMEM_TOTAL);

    // launch order chosen so the 4th launch (ncu capture slot) is k_gemm<2>
    k_cvt<<<HID_BLOCKS + 64, 256>>>(hidden, emb);                  // 1
    k_tsplit_both<<<dim3(32, 32, 2 * CC), dim3(32, 8)>>>(Wq, Wk);  // 2
    k_gemm<0><<<dim3(8, 8, CC), NT, SMEM_TOTAL>>>(nullptr);        // 3: McT
    k_gemm<2><<<dim3(8, 256, CC), NT, SMEM_TOTAL>>>(nullptr);      // 4: T  <- ncu
    k_gemm<1><<<dim3(8, 1, CC), NT, SMEM_TOTAL>>>(nullptr);        // 5: E
    k_wvsum<<<dim3(HH / 256, CC), 256>>>(Wv);                      // 6
    k_vsum<<<(BB * SS) / 8, 256>>>(hidden);                        // 7
    k_gemm<3><<<dim3(16, 17, CC * BB), NT, SMEM_TOTAL>>>(out);     // 8: scores
}

// round 10
// speedup vs baseline: 1.7709x; 1.7706x over previous
#include <cuda_runtime.h>
#include <cuda_bf16.h>
#include <cuda_fp16.h>
#include <cstdint>

#define CC 2
#define FF 32
#define HH 1024
#define BB 16
#define SS 2048
#define SF (SS + FF)   // 2080
#define NC 16          // K chunks of 64
#define SRB 144        // smem row bytes (128 data + 16 pad)
// 3-split bf16 GEMM staging (modes 0-2): Ahi,Alo,Bhi,Blo = 4 x 128 rows
#define OFF_AH 0
#define OFF_AL (128 * SRB)
#define OFF_BH (256 * SRB)
#define OFF_BL (512 * SRB)
#define STGB (768 * SRB)            // 110592
#define SMEM_G (2 * STGB)           // 221184
// fp16 main GEMM staging: A 128 rows + B 256 rows
#define OFF_B (128 * SRB)
#define STG_M (384 * SRB)           // 55296
#define NSTG_M 4
#define SMEM_M (NSTG_M * STG_M)     // 221184
#define NT 512

typedef __nv_bfloat16 bf16;
typedef __half fp16;

// ------------------------------ device scratch ----------------------------
__device__ bf16 g_hidH[(size_t)BB * SS * HH], g_hidL[(size_t)BB * SS * HH];
__device__ fp16 g_hidF[(size_t)BB * SS * HH];
__device__ bf16 g_WqTH[(size_t)CC * HH * HH], g_WqTL[(size_t)CC * HH * HH];
__device__ bf16 g_WkTH[(size_t)CC * HH * HH], g_WkTL[(size_t)CC * HH * HH];
__device__ bf16 g_McTH[(size_t)CC * HH * HH], g_McTL[(size_t)CC * HH * HH];
__device__ bf16 g_embPH[(size_t)CC * 128 * HH], g_embPL[(size_t)CC * 128 * HH];  // rows>=32 stay 0
__device__ fp16 g_EPf[(size_t)CC * 128 * HH];
__device__ fp16 g_Tf[(size_t)CC * BB * SS * HH];
__device__ float g_wvs[CC * HH];
__device__ float g_vsum[(size_t)CC * BB * SS];

// ------------------------------ helpers -----------------------------------
__device__ __forceinline__ uint32_t smem_to_u32(const void* p) {
    uint32_t a;
    asm("{ .reg .u64 t; cvta.to.shared.u64 t, %1; cvt.u32.u64 %0, t; }" : "=r"(a) : "l"(p));
    return a;
}
__device__ __forceinline__ void split2(float x, bf16& h, bf16& l) {
    h = __float2bfloat16(x);
    l = __float2bfloat16(x - __bfloat162float(h));
}
__device__ __forceinline__ uint32_t packbf(bf16 a, bf16 b) {
    return (uint32_t)__bfloat16_as_ushort(a) | ((uint32_t)__bfloat16_as_ushort(b) << 16);
}
__device__ __forceinline__ uint32_t packh(float a, float b) {
    __half2 h = __floats2half2_rn(a, b);
    return *(uint32_t*)&h;
}
__device__ __forceinline__ void ldsm4(uint32_t* r, uint32_t addr) {
    asm volatile("ldmatrix.sync.aligned.m8n8.x4.shared.b16 {%0,%1,%2,%3}, [%4];"
                 : "=r"(r[0]), "=r"(r[1]), "=r"(r[2]), "=r"(r[3]) : "r"(addr));
}
__device__ __forceinline__ void mma_bf16(float* c, const uint32_t* a, uint32_t b0, uint32_t b1) {
    asm volatile(
        "mma.sync.aligned.m16n8k16.row.col.f32.bf16.bf16.f32 "
        "{%0,%1,%2,%3},{%4,%5,%6,%7},{%8,%9},{%0,%1,%2,%3};"
        : "+f"(c[0]), "+f"(c[1]), "+f"(c[2]), "+f"(c[3])
        : "r"(a[0]), "r"(a[1]), "r"(a[2]), "r"(a[3]), "r"(b0), "r"(b1));
}
__device__ __forceinline__ void mma_fp16(float* c, const uint32_t* a, uint32_t b0, uint32_t b1) {
    asm volatile(
        "mma.sync.aligned.m16n8k16.row.col.f32.f16.f16.f32 "
        "{%0,%1,%2,%3},{%4,%5,%6,%7},{%8,%9},{%0,%1,%2,%3};"
        : "+f"(c[0]), "+f"(c[1]), "+f"(c[2]), "+f"(c[3])
        : "r"(a[0]), "r"(a[1]), "r"(a[2]), "r"(a[3]), "r"(b0), "r"(b1));
}
#define CPA(s, g) asm volatile("cp.async.cg.shared.global [%0], [%1], 16;" :: "r"(s), "l"(g))
#define CPA_COMMIT() asm volatile("cp.async.commit_group;" ::: "memory")
#define CPA_WAIT3() asm volatile("cp.async.wait_group 3;" ::: "memory")
#define CPA_WAIT2() asm volatile("cp.async.wait_group 2;" ::: "memory")
#define CPA_WAIT1() asm volatile("cp.async.wait_group 1;" ::: "memory")
#define CPA_WAIT0() asm volatile("cp.async.wait_group 0;" ::: "memory")

// ------------------------------ prep kernels ------------------------------
#define HID_BLOCKS 32768   // (BB*SS*HH/4)/256
__global__ void k_cvt(const float* __restrict__ hidden, const float* __restrict__ emb) {
    int bid = blockIdx.x;
    if (bid < HID_BLOCKS) {
        size_t i = (size_t)bid * 256 + threadIdx.x;
        float4 v = ((const float4*)hidden)[i];
        bf16 h0, l0, h1, l1, h2, l2, h3, l3;
        split2(v.x, h0, l0); split2(v.y, h1, l1); split2(v.z, h2, l2); split2(v.w, h3, l3);
        ((uint32_t*)g_hidH)[2 * i] = packbf(h0, h1);
        ((uint32_t*)g_hidH)[2 * i + 1] = packbf(h2, h3);
        ((uint32_t*)g_hidL)[2 * i] = packbf(l0, l1);
        ((uint32_t*)g_hidL)[2 * i + 1] = packbf(l2, l3);
        ((uint32_t*)g_hidF)[2 * i] = packh(v.x, v.y);
        ((uint32_t*)g_hidF)[2 * i + 1] = packh(v.z, v.w);
    } else {
        int i = (bid - HID_BLOCKS) * 256 + threadIdx.x;
        int e = i * 4;
        int c = e / (FF * HH);
        int rem = e - c * FF * HH;
        int f = rem / HH, h = rem - f * HH;
        float4 v = ((const float4*)emb)[i];
        bf16 h0, l0, h1, l1, h2, l2, h3, l3;
        split2(v.x, h0, l0); split2(v.y, h1, l1); split2(v.z, h2, l2); split2(v.w, h3, l3);
        size_t o = ((size_t)c * 128 + f) * HH + h;
        *(uint32_t*)&g_embPH[o] = packbf(h0, h1);
        *(uint32_t*)&g_embPH[o + 2] = packbf(h2, h3);
        *(uint32_t*)&g_embPL[o] = packbf(l0, l1);
        *(uint32_t*)&g_embPL[o + 2] = packbf(l2, l3);
    }
}

__global__ void k_tsplit_both(const float* __restrict__ Wq, const float* __restrict__ Wk) {
    __shared__ float t[32][33];
    int z = blockIdx.z;
    int c = z >> 1, W = z & 1;
    const float* I = (W == 0 ? Wq : Wk) + (size_t)c * HH * HH;
    bf16* OH = (W == 0 ? g_WqTH : g_WkTH) + (size_t)c * HH * HH;
    bf16* OL = (W == 0 ? g_WqTL : g_WkTL) + (size_t)c * HH * HH;
    int x = blockIdx.x * 32 + threadIdx.x;
#pragma unroll
    for (int i = threadIdx.y; i < 32; i += 8)
        t[i][threadIdx.x] = I[(size_t)(blockIdx.y * 32 + i) * HH + x];
    __syncthreads();
    int ox = blockIdx.y * 32 + threadIdx.x;
#pragma unroll
    for (int i = threadIdx.y; i < 32; i += 8) {
        float v = t[threadIdx.x][i];
        bf16 h, l;
        split2(v, h, l);
        size_t o = (size_t)(blockIdx.x * 32 + i) * HH + ox;
        OH[o] = h;
        OL[o] = l;
    }
}

__global__ void k_wvsum(const float* __restrict__ Wv) {
    int c = blockIdx.y;
    int h = blockIdx.x * 256 + threadIdx.x;
    const float* W = Wv + (size_t)c * HH * HH;
    float a = 0.f;
#pragma unroll 8
    for (int o = 0; o < HH; ++o) a += W[(size_t)o * HH + h];
    g_wvs[c * HH + h] = a;
}

__global__ void k_vsum(const float* __restrict__ hidden) {
    int w = (blockIdx.x * blockDim.x + threadIdx.x) >> 5;
    int lane = threadIdx.x & 31;
    if (w >= BB * SS) return;
    const float* hr = hidden + (size_t)w * HH;
    float a0 = 0.f, a1 = 0.f;
#pragma unroll 4
    for (int i = lane; i < HH; i += 32) {
        float hv = hr[i];
        a0 += hv * g_wvs[i];
        a1 += hv * g_wvs[HH + i];
    }
#pragma unroll
    for (int off = 16; off; off >>= 1) {
        a0 += __shfl_down_sync(0xFFFFFFFFu, a0, off);
        a1 += __shfl_down_sync(0xFFFFFFFFu, a1, off);
    }
    if (lane == 0) {
        g_vsum[w] = a0;
        g_vsum[(size_t)BB * SS + w] = a1;
    }
}

// ------------------------------ 3-split bf16 GEMM (modes 0-2) -------------
// C[128,256] = (Ahi+Alo).(Bhi+Blo)^T, 16 warps, warp tile 64x32, 2-stage.
// MODE 0: McT (bf16 hi/lo out)  1: E (fp16 out)  2: T (fp16 out)
template <int MODE>
__global__ void __launch_bounds__(NT, 1) k_gemm() {
    extern __shared__ __align__(128) char smem[];
    const uint32_t sb = smem_to_u32(smem);
    const int tid = threadIdx.x, wid = tid >> 5, lane = tid & 31;
    const int bx = blockIdx.x, by = blockIdx.y, bz = blockIdx.z;

    const bf16 *AH, *AL, *BH, *BL;
    if (MODE == 0) {
        size_t cb = (size_t)bz * HH * HH;
        AH = g_WkTH + cb + (size_t)by * 128 * HH; AL = g_WkTL + cb + (size_t)by * 128 * HH;
        BH = g_WqTH + cb + (size_t)bx * 256 * HH; BL = g_WqTL + cb + (size_t)bx * 256 * HH;
    } else if (MODE == 1) {
        AH = g_embPH + (size_t)bz * 128 * HH; AL = g_embPL + (size_t)bz * 128 * HH;
        size_t cb = (size_t)bz * HH * HH;
        BH = g_WkTH + cb + (size_t)bx * 256 * HH; BL = g_WkTL + cb + (size_t)bx * 256 * HH;
    } else {
        AH = g_hidH + (size_t)by * 128 * HH; AL = g_hidL + (size_t)by * 128 * HH;
        size_t cb = (size_t)bz * HH * HH;
        BH = g_McTH + cb + (size_t)bx * 256 * HH; BL = g_McTL + cb + (size_t)bx * 256 * HH;
    }

    // loaders: A 4 thr/row (32B), B 2 thr/row (64B)
    const int arow = tid >> 2, aq = tid & 3;
    const uint32_t sAOff = (uint32_t)(arow * SRB + aq * 32);
    const size_t gAOff = (size_t)arow * HH + aq * 16;
    const int brow = tid >> 1, bhalf = tid & 1;
    const uint32_t sBOff = (uint32_t)(brow * SRB + bhalf * 64);
    const size_t gBOff = (size_t)brow * HH + bhalf * 32;

    const int wm = wid >> 3, wn = wid & 7;
    const uint32_t aOff = (uint32_t)((wm * 64 + (lane & 15)) * SRB + ((lane >> 4) << 4));
    const uint32_t bOff = (uint32_t)((wn * 32 + (lane & 7) + ((lane >> 4) & 1) * 8) * SRB +
                                     (((lane >> 3) & 1) << 4));

    float acc[4][4][4] = {};

    {
#pragma unroll
        for (int i = 0; i < 2; i++) {
            CPA(sb + OFF_AH + sAOff + i * 16, AH + gAOff + i * 8);
            CPA(sb + OFF_AL + sAOff + i * 16, AL + gAOff + i * 8);
        }
#pragma unroll
        for (int i = 0; i < 4; i++) {
            CPA(sb + OFF_BH + sBOff + i * 16, BH + gBOff + i * 8);
            CPA(sb + OFF_BL + sBOff + i * 16, BL + gBOff + i * 8);
        }
        CPA_COMMIT();
    }

    for (int ck = 0; ck < NC; ck++) {
        if (ck + 1 < NC) {
            const uint32_t stg = sb + ((ck + 1) & 1) * STGB;
            const int kof = (ck + 1) * 64;
#pragma unroll
            for (int i = 0; i < 2; i++) {
                CPA(stg + OFF_AH + sAOff + i * 16, AH + gAOff + kof + i * 8);
                CPA(stg + OFF_AL + sAOff + i * 16, AL + gAOff + kof + i * 8);
            }
#pragma unroll
            for (int i = 0; i < 4; i++) {
                CPA(stg + OFF_BH + sBOff + i * 16, BH + gBOff + kof + i * 8);
                CPA(stg + OFF_BL + sBOff + i * 16, BL + gBOff + kof + i * 8);
            }
            CPA_COMMIT();
            CPA_WAIT1();
        } else {
            CPA_WAIT0();
        }
        __syncthreads();

        const uint32_t base = sb + (ck & 1) * STGB;
        const uint32_t pAH = base + OFF_AH + aOff, pAL = base + OFF_AL + aOff;
        const uint32_t pBH = base + OFF_BH + bOff, pBL = base + OFF_BL + bOff;
#pragma unroll
        for (int ka = 0; ka < 4; ka++) {
            uint32_t A[4][4], Bh[2][4], Bl[2][4];
#pragma unroll
            for (int m = 0; m < 4; m++) ldsm4(A[m], pAH + m * (16 * SRB) + ka * 32);
#pragma unroll
            for (int nb = 0; nb < 2; nb++) ldsm4(Bh[nb], pBH + nb * (16 * SRB) + ka * 32);
#pragma unroll
            for (int m = 0; m < 4; m++)
#pragma unroll
                for (int n8 = 0; n8 < 4; n8++)
                    mma_bf16(acc[m][n8], A[m], Bh[n8 >> 1][(n8 & 1) * 2], Bh[n8 >> 1][(n8 & 1) * 2 + 1]);
#pragma unroll
            for (int nb = 0; nb < 2; nb++) ldsm4(Bl[nb], pBL + nb * (16 * SRB) + ka * 32);
#pragma unroll
            for (int m = 0; m < 4; m++)
#pragma unroll
                for (int n8 = 0; n8 < 4; n8++)
                    mma_bf16(acc[m][n8], A[m], Bl[n8 >> 1][(n8 & 1) * 2], Bl[n8 >> 1][(n8 & 1) * 2 + 1]);
#pragma unroll
            for (int m = 0; m < 4; m++) ldsm4(A[m], pAL + m * (16 * SRB) + ka * 32);
#pragma unroll
            for (int m = 0; m < 4; m++)
#pragma unroll
                for (int n8 = 0; n8 < 4; n8++)
                    mma_bf16(acc[m][n8], A[m], Bh[n8 >> 1][(n8 & 1) * 2], Bh[n8 >> 1][(n8 & 1) * 2 + 1]);
        }
        __syncthreads();
    }

    // epilogue
    const int rBase = wm * 64 + (lane >> 2);
    const int cBase = wn * 32 + (lane & 3) * 2;
    if (MODE == 0) {
#pragma unroll
        for (int m = 0; m < 4; m++) {
            int r0 = m * 16 + rBase;
#pragma unroll
            for (int n8 = 0; n8 < 4; n8++) {
                int cc = bx * 256 + cBase + n8 * 8;
                size_t rowB = (size_t)bz * HH * HH + (size_t)(by * 128) * HH;
                bf16 h0, l0, h1, l1;
                split2(acc[m][n8][0], h0, l0);
                split2(acc[m][n8][1], h1, l1);
                *(uint32_t*)&g_McTH[rowB + (size_t)r0 * HH + cc] = packbf(h0, h1);
                *(uint32_t*)&g_McTL[rowB + (size_t)r0 * HH + cc] = packbf(l0, l1);
                split2(acc[m][n8][2], h0, l0);
                split2(acc[m][n8][3], h1, l1);
                *(uint32_t*)&g_McTH[rowB + (size_t)(r0 + 8) * HH + cc] = packbf(h0, h1);
                *(uint32_t*)&g_McTL[rowB + (size_t)(r0 + 8) * HH + cc] = packbf(l0, l1);
            }
        }
    } else {
        fp16* O = (MODE == 1) ? g_EPf : g_Tf;
        size_t rowB = (MODE == 1) ? (size_t)bz * 128 * HH
                                  : ((size_t)bz * BB * SS + (size_t)by * 128) * HH;
#pragma unroll
        for (int m = 0; m < 4; m++) {
            int r0 = m * 16 + rBase;
#pragma unroll
            for (int n8 = 0; n8 < 4; n8++) {
                int cc = bx * 256 + cBase + n8 * 8;
                *(uint32_t*)&O[rowB + (size_t)r0 * HH + cc] = packh(acc[m][n8][0], acc[m][n8][1]);
                *(uint32_t*)&O[rowB + (size_t)(r0 + 8) * HH + cc] = packh(acc[m][n8][2], acc[m][n8][3]);
            }
        }
    }
}

// ------------------------------ fp16 main GEMM ----------------------------
// out[b,c,i,j] = ([Tf;Ef] . hidF^T)[i,j] * vsum[j], single fp16 pass.
// CTA tile 128x256, 16 warps (2x8), warp tile 64x32, 4-stage cp.async.
__global__ void __launch_bounds__(NT, 1) k_main(float* __restrict__ out) {
    extern __shared__ __align__(128) char smem[];
    const uint32_t sb = smem_to_u32(smem);
    const int tid = threadIdx.x, wid = tid >> 5, lane = tid & 31;
    const int bx = blockIdx.x, by = blockIdx.y, bz = blockIdx.z;
    const int c = bz >> 4, b = bz & 15;

    const fp16* Af = (by < 16)
        ? g_Tf + ((size_t)c * BB * SS + (size_t)b * SS + (size_t)by * 128) * HH
        : g_EPf + (size_t)c * 128 * HH;
    const fp16* Bf = g_hidF + ((size_t)b * SS + (size_t)bx * 256) * HH;

    // loaders: A 4 thr/row (2x16B), B 2 thr/row (4x16B)
    const int arow = tid >> 2, aq = tid & 3;
    const uint32_t sAOff = (uint32_t)(arow * SRB + aq * 32);
    const size_t gAOff = (size_t)arow * HH + aq * 16;
    const int brow = tid >> 1, bhalf = tid & 1;
    const uint32_t sBOff = (uint32_t)(OFF_B + brow * SRB + bhalf * 64);
    const size_t gBOff = (size_t)brow * HH + bhalf * 32;

    const int wm = wid >> 3, wn = wid & 7;
    const uint32_t aOff = (uint32_t)((wm * 64 + (lane & 15)) * SRB + ((lane >> 4) << 4));
    const uint32_t bOff = (uint32_t)(OFF_B + (wn * 32 + (lane & 7) + ((lane >> 4) & 1) * 8) * SRB +
                                     (((lane >> 3) & 1) << 4));

    float acc[4][4][4] = {};

    // prologue: chunks 0..2 -> stages 0..2
#pragma unroll
    for (int pc = 0; pc < 3; pc++) {
        const uint32_t stg = sb + pc * STG_M;
        const int kof = pc * 64;
#pragma unroll
        for (int i = 0; i < 2; i++) CPA(stg + sAOff + i * 16, Af + gAOff + kof + i * 8);
#pragma unroll
        for (int i = 0; i < 4; i++) CPA(stg + sBOff + i * 16, Bf + gBOff + kof + i * 8);
        CPA_COMMIT();
    }

    int stage = 0;
    for (int ck = 0; ck < NC; ck++) {
        if (ck + 3 < NC) {
            const uint32_t stg = sb + ((stage + 3) & 3) * STG_M;
            const int kof = (ck + 3) * 64;
#pragma unroll
            for (int i = 0; i < 2; i++) CPA(stg + sAOff + i * 16, Af + gAOff + kof + i * 8);
#pragma unroll
            for (int i = 0; i < 4; i++) CPA(stg + sBOff + i * 16, Bf + gBOff + kof + i * 8);
            CPA_COMMIT();
            CPA_WAIT3();
        } else if (ck + 2 < NC) {
            CPA_WAIT2();
        } else if (ck + 1 < NC) {
            CPA_WAIT1();
        } else {
            CPA_WAIT0();
        }
        __syncthreads();

        const uint32_t pA = sb + stage * STG_M + aOff;
        const uint32_t pB = sb + stage * STG_M + bOff;

        uint32_t A[2][4][4], Bq[2][2][4];
#pragma unroll
        for (int m = 0; m < 4; m++) ldsm4(A[0][m], pA + m * (16 * SRB));
#pragma unroll
        for (int nb = 0; nb < 2; nb++) ldsm4(Bq[0][nb], pB + nb * (16 * SRB));
#pragma unroll
        for (int ka = 0; ka < 4; ka++) {
            const int cur = ka & 1, nxt = cur ^ 1;
            if (ka < 3) {
                const uint32_t ko = (ka + 1) * 32;
#pragma unroll
                for (int m = 0; m < 4; m++) ldsm4(A[nxt][m], pA + m * (16 * SRB) + ko);
#pragma unroll
                for (int nb = 0; nb < 2; nb++) ldsm4(Bq[nxt][nb], pB + nb * (16 * SRB) + ko);
            }
#pragma unroll
            for (int m = 0; m < 4; m++)
#pragma unroll
                for (int n8 = 0; n8 < 4; n8++)
                    mma_fp16(acc[m][n8], A[cur][m],
                             Bq[cur][n8 >> 1][(n8 & 1) * 2], Bq[cur][n8 >> 1][(n8 & 1) * 2 + 1]);
        }
        __syncthreads();
        stage = (stage + 1) & 3;
    }

    // epilogue: multiply by vsum, store fp32
    const int rBase = wm * 64 + (lane >> 2);
    const int cBase = wn * 32 + (lane & 3) * 2;
    const float* vsp = g_vsum + ((size_t)c * BB + b) * SS + bx * 256;
    float* ob = out + ((size_t)b * CC + c) * SF * SS;
#pragma unroll
    for (int m = 0; m < 4; m++) {
        int r0 = by * 128 + m * 16 + rBase;
#pragma unroll
        for (int n8 = 0; n8 < 4; n8++) {
            int cc = cBase + n8 * 8;
            float2 vs = *(const float2*)(vsp + cc);
            size_t col = (size_t)bx * 256 + cc;
            if (r0 < SF) {
                float2 o;
                o.x = acc[m][n8][0] * vs.x;
                o.y = acc[m][n8][1] * vs.y;
                *(float2*)(ob + (size_t)r0 * SS + col) = o;
            }
            if (r0 + 8 < SF) {
                float2 o;
                o.x = acc[m][n8][2] * vs.x;
                o.y = acc[m][n8][3] * vs.y;
                *(float2*)(ob + (size_t)(r0 + 8) * SS + col) = o;
            }
        }
    }
}

// ------------------------------ launch ------------------------------------
extern "C" void kernel_launch(void* const* d_in, const int* in_sizes, int n_in,
                              void* d_out, int out_size) {
    const float* hidden = (const float*)d_in[0];
    const float* emb    = (const float*)d_in[1];
    const float* Wk     = (const float*)d_in[2];
    const float* Wq     = (const float*)d_in[3];
    const float* Wv     = (const float*)d_in[4];
    float* out = (float*)d_out;

    cudaFuncSetAttribute(k_gemm<0>, cudaFuncAttributeMaxDynamicSharedMemorySize, SMEM_G);
    cudaFuncSetAttribute(k_gemm<1>, cudaFuncAttributeMaxDynamicSharedMemorySize, SMEM_G);
    cudaFuncSetAttribute(k_gemm<2>, cudaFuncAttributeMaxDynamicSharedMemorySize, SMEM_G);
    cudaFuncSetAttribute(k_main, cudaFuncAttributeMaxDynamicSharedMemorySize, SMEM_M);

    // launch order chosen so the 4th launch (ncu capture slot) is k_gemm<2>
    k_cvt<<<HID_BLOCKS + 64, 256>>>(hidden, emb);                  // 1
    k_tsplit_both<<<dim3(32, 32, 2 * CC), dim3(32, 8)>>>(Wq, Wk);  // 2
    k_gemm<0><<<dim3(4, 8, CC), NT, SMEM_G>>>();                   // 3: McT
    k_gemm<2><<<dim3(4, 256, CC), NT, SMEM_G>>>();                 // 4: T  <- ncu
    k_gemm<1><<<dim3(4, 1, CC), NT, SMEM_G>>>();                   // 5: E
    k_wvsum<<<dim3(HH / 256, CC), 256>>>(Wv);                      // 6
    k_vsum<<<(BB * SS) / 8, 256>>>(hidden);                        // 7
    k_main<<<dim3(8, 17, CC * BB), NT, SMEM_M>>>(out);             // 8: scores
}

// round 11
// speedup vs baseline: 2.3608x; 1.3332x over previous
#include <cuda_runtime.h>
#include <cuda_bf16.h>
#include <cuda_fp16.h>
#include <cstdint>

#define CC 2
#define FF 32
#define HH 1024
#define BB 16
#define SS 2048
#define SF (SS + FF)   // 2080
#define NC 16          // K chunks of 64
#define SRB 144        // smem row bytes (128 data + 16 pad)
// 3-split bf16 GEMM staging (modes 0-1): Ahi,Alo,Bhi,Blo = 4 x {128,256} rows
#define OFF_AH 0
#define OFF_AL (128 * SRB)
#define OFF_BH (256 * SRB)
#define OFF_BL (512 * SRB)
#define STGB (768 * SRB)            // 110592
#define SMEM_G (2 * STGB)           // 221184
// fp16 GEMM staging: A 128 rows + B 256 rows
#define OFF_B (128 * SRB)
#define STG_M (384 * SRB)           // 55296
#define NSTG_M 4
#define SMEM_M (NSTG_M * STG_M)     // 221184
#define NT 512

typedef __nv_bfloat16 bf16;
typedef __half fp16;

// ------------------------------ device scratch ----------------------------
__device__ fp16 g_hidF[(size_t)BB * SS * HH];
__device__ bf16 g_WqTH[(size_t)CC * HH * HH], g_WqTL[(size_t)CC * HH * HH];
__device__ bf16 g_WkTH[(size_t)CC * HH * HH], g_WkTL[(size_t)CC * HH * HH];
__device__ fp16 g_McTf[(size_t)CC * HH * HH];
__device__ bf16 g_embPH[(size_t)CC * 128 * HH], g_embPL[(size_t)CC * 128 * HH];  // rows>=32 stay 0
__device__ fp16 g_EPf[(size_t)CC * 128 * HH];
__device__ fp16 g_Tf[(size_t)CC * BB * SS * HH];
__device__ float g_wvs[CC * HH];
__device__ float g_vsum[(size_t)CC * BB * SS];

// ------------------------------ helpers -----------------------------------
__device__ __forceinline__ uint32_t smem_to_u32(const void* p) {
    uint32_t a;
    asm("{ .reg .u64 t; cvta.to.shared.u64 t, %1; cvt.u32.u64 %0, t; }" : "=r"(a) : "l"(p));
    return a;
}
__device__ __forceinline__ void split2(float x, bf16& h, bf16& l) {
    h = __float2bfloat16(x);
    l = __float2bfloat16(x - __bfloat162float(h));
}
__device__ __forceinline__ uint32_t packbf(bf16 a, bf16 b) {
    return (uint32_t)__bfloat16_as_ushort(a) | ((uint32_t)__bfloat16_as_ushort(b) << 16);
}
__device__ __forceinline__ uint32_t packh(float a, float b) {
    __half2 h = __floats2half2_rn(a, b);
    return *(uint32_t*)&h;
}
__device__ __forceinline__ void ldsm4(uint32_t* r, uint32_t addr) {
    asm volatile("ldmatrix.sync.aligned.m8n8.x4.shared.b16 {%0,%1,%2,%3}, [%4];"
                 : "=r"(r[0]), "=r"(r[1]), "=r"(r[2]), "=r"(r[3]) : "r"(addr));
}
__device__ __forceinline__ void mma_bf16(float* c, const uint32_t* a, uint32_t b0, uint32_t b1) {
    asm volatile(
        "mma.sync.aligned.m16n8k16.row.col.f32.bf16.bf16.f32 "
        "{%0,%1,%2,%3},{%4,%5,%6,%7},{%8,%9},{%0,%1,%2,%3};"
        : "+f"(c[0]), "+f"(c[1]), "+f"(c[2]), "+f"(c[3])
        : "r"(a[0]), "r"(a[1]), "r"(a[2]), "r"(a[3]), "r"(b0), "r"(b1));
}
__device__ __forceinline__ void mma_fp16(float* c, const uint32_t* a, uint32_t b0, uint32_t b1) {
    asm volatile(
        "mma.sync.aligned.m16n8k16.row.col.f32.f16.f16.f32 "
        "{%0,%1,%2,%3},{%4,%5,%6,%7},{%8,%9},{%0,%1,%2,%3};"
        : "+f"(c[0]), "+f"(c[1]), "+f"(c[2]), "+f"(c[3])
        : "r"(a[0]), "r"(a[1]), "r"(a[2]), "r"(a[3]), "r"(b0), "r"(b1));
}
#define CPA(s, g) asm volatile("cp.async.cg.shared.global [%0], [%1], 16;" :: "r"(s), "l"(g))
#define CPA_COMMIT() asm volatile("cp.async.commit_group;" ::: "memory")
#define CPA_WAIT3() asm volatile("cp.async.wait_group 3;" ::: "memory")
#define CPA_WAIT2() asm volatile("cp.async.wait_group 2;" ::: "memory")
#define CPA_WAIT1() asm volatile("cp.async.wait_group 1;" ::: "memory")
#define CPA_WAIT0() asm volatile("cp.async.wait_group 0;" ::: "memory")

// ------------------------------ prep kernels ------------------------------
#define HID_BLOCKS 32768   // (BB*SS*HH/4)/256
__global__ void k_cvt(const float* __restrict__ hidden, const float* __restrict__ emb) {
    int bid = blockIdx.x;
    if (bid < HID_BLOCKS) {
        size_t i = (size_t)bid * 256 + threadIdx.x;
        float4 v = ((const float4*)hidden)[i];
        ((uint32_t*)g_hidF)[2 * i] = packh(v.x, v.y);
        ((uint32_t*)g_hidF)[2 * i + 1] = packh(v.z, v.w);
    } else {
        int i = (bid - HID_BLOCKS) * 256 + threadIdx.x;
        int e = i * 4;
        int c = e / (FF * HH);
        int rem = e - c * FF * HH;
        int f = rem / HH, h = rem - f * HH;
        float4 v = ((const float4*)emb)[i];
        bf16 h0, l0, h1, l1, h2, l2, h3, l3;
        split2(v.x, h0, l0); split2(v.y, h1, l1); split2(v.z, h2, l2); split2(v.w, h3, l3);
        size_t o = ((size_t)c * 128 + f) * HH + h;
        *(uint32_t*)&g_embPH[o] = packbf(h0, h1);
        *(uint32_t*)&g_embPH[o + 2] = packbf(h2, h3);
        *(uint32_t*)&g_embPL[o] = packbf(l0, l1);
        *(uint32_t*)&g_embPL[o + 2] = packbf(l2, l3);
    }
}

__global__ void k_tsplit_both(const float* __restrict__ Wq, const float* __restrict__ Wk) {
    __shared__ float t[32][33];
    int z = blockIdx.z;
    int c = z >> 1, W = z & 1;
    const float* I = (W == 0 ? Wq : Wk) + (size_t)c * HH * HH;
    bf16* OH = (W == 0 ? g_WqTH : g_WkTH) + (size_t)c * HH * HH;
    bf16* OL = (W == 0 ? g_WqTL : g_WkTL) + (size_t)c * HH * HH;
    int x = blockIdx.x * 32 + threadIdx.x;
#pragma unroll
    for (int i = threadIdx.y; i < 32; i += 8)
        t[i][threadIdx.x] = I[(size_t)(blockIdx.y * 32 + i) * HH + x];
    __syncthreads();
    int ox = blockIdx.y * 32 + threadIdx.x;
#pragma unroll
    for (int i = threadIdx.y; i < 32; i += 8) {
        float v = t[threadIdx.x][i];
        bf16 h, l;
        split2(v, h, l);
        size_t o = (size_t)(blockIdx.x * 32 + i) * HH + ox;
        OH[o] = h;
        OL[o] = l;
    }
}

__global__ void k_wvsum(const float* __restrict__ Wv) {
    int c = blockIdx.y;
    int h = blockIdx.x * 256 + threadIdx.x;
    const float* W = Wv + (size_t)c * HH * HH;
    float a = 0.f;
#pragma unroll 8
    for (int o = 0; o < HH; ++o) a += W[(size_t)o * HH + h];
    g_wvs[c * HH + h] = a;
}

__global__ void k_vsum(const float* __restrict__ hidden) {
    int w = (blockIdx.x * blockDim.x + threadIdx.x) >> 5;
    int lane = threadIdx.x & 31;
    if (w >= BB * SS) return;
    const float* hr = hidden + (size_t)w * HH;
    float a0 = 0.f, a1 = 0.f;
#pragma unroll 4
    for (int i = lane; i < HH; i += 32) {
        float hv = hr[i];
        a0 += hv * g_wvs[i];
        a1 += hv * g_wvs[HH + i];
    }
#pragma unroll
    for (int off = 16; off; off >>= 1) {
        a0 += __shfl_down_sync(0xFFFFFFFFu, a0, off);
        a1 += __shfl_down_sync(0xFFFFFFFFu, a1, off);
    }
    if (lane == 0) {
        g_vsum[w] = a0;
        g_vsum[(size_t)BB * SS + w] = a1;
    }
}

// ------------------------------ 3-split bf16 GEMM (modes 0-1) -------------
// C[128,256] = (Ahi+Alo).(Bhi+Blo)^T, 16 warps, warp tile 64x32, 2-stage.
// MODE 0: McT (fp16 out)   1: E (fp16 out)
template <int MODE>
__global__ void __launch_bounds__(NT, 1) k_gemm() {
    extern __shared__ __align__(128) char smem[];
    const uint32_t sb = smem_to_u32(smem);
    const int tid = threadIdx.x, wid = tid >> 5, lane = tid & 31;
    const int bx = blockIdx.x, by = blockIdx.y, bz = blockIdx.z;

    const bf16 *AH, *AL, *BH, *BL;
    if (MODE == 0) {
        size_t cb = (size_t)bz * HH * HH;
        AH = g_WkTH + cb + (size_t)by * 128 * HH; AL = g_WkTL + cb + (size_t)by * 128 * HH;
        BH = g_WqTH + cb + (size_t)bx * 256 * HH; BL = g_WqTL + cb + (size_t)bx * 256 * HH;
    } else {
        AH = g_embPH + (size_t)bz * 128 * HH; AL = g_embPL + (size_t)bz * 128 * HH;
        size_t cb = (size_t)bz * HH * HH;
        BH = g_WkTH + cb + (size_t)bx * 256 * HH; BL = g_WkTL + cb + (size_t)bx * 256 * HH;
    }

    // loaders: A 4 thr/row (32B), B 2 thr/row (64B)
    const int arow = tid >> 2, aq = tid & 3;
    const uint32_t sAOff = (uint32_t)(arow * SRB + aq * 32);
    const size_t gAOff = (size_t)arow * HH + aq * 16;
    const int brow = tid >> 1, bhalf = tid & 1;
    const uint32_t sBOff = (uint32_t)(brow * SRB + bhalf * 64);
    const size_t gBOff = (size_t)brow * HH + bhalf * 32;

    const int wm = wid >> 3, wn = wid & 7;
    const uint32_t aOff = (uint32_t)((wm * 64 + (lane & 15)) * SRB + ((lane >> 4) << 4));
    const uint32_t bOff = (uint32_t)((wn * 32 + (lane & 7) + ((lane >> 4) & 1) * 8) * SRB +
                                     (((lane >> 3) & 1) << 4));

    float acc[4][4][4] = {};

    {
#pragma unroll
        for (int i = 0; i < 2; i++) {
            CPA(sb + OFF_AH + sAOff + i * 16, AH + gAOff + i * 8);
            CPA(sb + OFF_AL + sAOff + i * 16, AL + gAOff + i * 8);
        }
#pragma unroll
        for (int i = 0; i < 4; i++) {
            CPA(sb + OFF_BH + sBOff + i * 16, BH + gBOff + i * 8);
            CPA(sb + OFF_BL + sBOff + i * 16, BL + gBOff + i * 8);
        }
        CPA_COMMIT();
    }

    for (int ck = 0; ck < NC; ck++) {
        if (ck + 1 < NC) {
            const uint32_t stg = sb + ((ck + 1) & 1) * STGB;
            const int kof = (ck + 1) * 64;
#pragma unroll
            for (int i = 0; i < 2; i++) {
                CPA(stg + OFF_AH + sAOff + i * 16, AH + gAOff + kof + i * 8);
                CPA(stg + OFF_AL + sAOff + i * 16, AL + gAOff + kof + i * 8);
            }
#pragma unroll
            for (int i = 0; i < 4; i++) {
                CPA(stg + OFF_BH + sBOff + i * 16, BH + gBOff + kof + i * 8);
                CPA(stg + OFF_BL + sBOff + i * 16, BL + gBOff + kof + i * 8);
            }
            CPA_COMMIT();
            CPA_WAIT1();
        } else {
            CPA_WAIT0();
        }
        __syncthreads();

        const uint32_t base = sb + (ck & 1) * STGB;
        const uint32_t pAH = base + OFF_AH + aOff, pAL = base + OFF_AL + aOff;
        const uint32_t pBH = base + OFF_BH + bOff, pBL = base + OFF_BL + bOff;
#pragma unroll
        for (int ka = 0; ka < 4; ka++) {
            uint32_t A[4][4], Bh[2][4], Bl[2][4];
#pragma unroll
            for (int m = 0; m < 4; m++) ldsm4(A[m], pAH + m * (16 * SRB) + ka * 32);
#pragma unroll
            for (int nb = 0; nb < 2; nb++) ldsm4(Bh[nb], pBH + nb * (16 * SRB) + ka * 32);
#pragma unroll
            for (int m = 0; m < 4; m++)
#pragma unroll
                for (int n8 = 0; n8 < 4; n8++)
                    mma_bf16(acc[m][n8], A[m], Bh[n8 >> 1][(n8 & 1) * 2], Bh[n8 >> 1][(n8 & 1) * 2 + 1]);
#pragma unroll
            for (int nb = 0; nb < 2; nb++) ldsm4(Bl[nb], pBL + nb * (16 * SRB) + ka * 32);
#pragma unroll
            for (int m = 0; m < 4; m++)
#pragma unroll
                for (int n8 = 0; n8 < 4; n8++)
                    mma_bf16(acc[m][n8], A[m], Bl[n8 >> 1][(n8 & 1) * 2], Bl[n8 >> 1][(n8 & 1) * 2 + 1]);
#pragma unroll
            for (int m = 0; m < 4; m++) ldsm4(A[m], pAL + m * (16 * SRB) + ka * 32);
#pragma unroll
            for (int m = 0; m < 4; m++)
#pragma unroll
                for (int n8 = 0; n8 < 4; n8++)
                    mma_bf16(acc[m][n8], A[m], Bh[n8 >> 1][(n8 & 1) * 2], Bh[n8 >> 1][(n8 & 1) * 2 + 1]);
        }
        __syncthreads();
    }

    // epilogue -> fp16
    const int rBase = wm * 64 + (lane >> 2);
    const int cBase = wn * 32 + (lane & 3) * 2;
    fp16* O = (MODE == 0) ? g_McTf : g_EPf;
    size_t rowB = (MODE == 0) ? (size_t)bz * HH * HH + (size_t)(by * 128) * HH
                              : (size_t)bz * 128 * HH;
#pragma unroll
    for (int m = 0; m < 4; m++) {
        int r0 = m * 16 + rBase;
#pragma unroll
        for (int n8 = 0; n8 < 4; n8++) {
            int cc = bx * 256 + cBase + n8 * 8;
            *(uint32_t*)&O[rowB + (size_t)r0 * HH + cc] = packh(acc[m][n8][0], acc[m][n8][1]);
            *(uint32_t*)&O[rowB + (size_t)(r0 + 8) * HH + cc] = packh(acc[m][n8][2], acc[m][n8][3]);
        }
    }
}

// ------------------------------ fp16 GEMM ---------------------------------
// OM 0: T = hidF . McTf^T          (fp16 out, grid: x=HH/256, y=BB*SS/128, z=CC)
// OM 1: out = ([Tf;EPf].hidF^T)*vsum (fp32 out, grid: x=SS/256, y=17, z=CC*BB)
// CTA tile 128x256, 16 warps (2x8), warp tile 64x32, 4-stage cp.async.
template <int OM>
__global__ void __launch_bounds__(NT, 1) k_fp16(float* __restrict__ out) {
    extern __shared__ __align__(128) char smem[];
    const uint32_t sb = smem_to_u32(smem);
    const int tid = threadIdx.x, wid = tid >> 5, lane = tid & 31;
    const int bx = blockIdx.x, by = blockIdx.y, bz = blockIdx.z;
    const int c = (OM == 1) ? (bz >> 4) : bz;
    const int b = (OM == 1) ? (bz & 15) : 0;

    const fp16 *Af, *Bf;
    if (OM == 0) {
        Af = g_hidF + (size_t)by * 128 * HH;
        Bf = g_McTf + (size_t)bz * HH * HH + (size_t)bx * 256 * HH;
    } else {
        Af = (by < 16)
            ? g_Tf + ((size_t)c * BB * SS + (size_t)b * SS + (size_t)by * 128) * HH
            : g_EPf + (size_t)c * 128 * HH;
        Bf = g_hidF + ((size_t)b * SS + (size_t)bx * 256) * HH;
    }

    // loaders: A 4 thr/row (2x16B), B 2 thr/row (4x16B)
    const int arow = tid >> 2, aq = tid & 3;
    const uint32_t sAOff = (uint32_t)(arow * SRB + aq * 32);
    const size_t gAOff = (size_t)arow * HH + aq * 16;
    const int brow = tid >> 1, bhalf = tid & 1;
    const uint32_t sBOff = (uint32_t)(OFF_B + brow * SRB + bhalf * 64);
    const size_t gBOff = (size_t)brow * HH + bhalf * 32;

    const int wm = wid >> 3, wn = wid & 7;
    const uint32_t aOff = (uint32_t)((wm * 64 + (lane & 15)) * SRB + ((lane >> 4) << 4));
    const uint32_t bOff = (uint32_t)(OFF_B + (wn * 32 + (lane & 7) + ((lane >> 4) & 1) * 8) * SRB +
                                     (((lane >> 3) & 1) << 4));

    float acc[4][4][4] = {};

    // prologue: chunks 0..2 -> stages 0..2
#pragma unroll
    for (int pc = 0; pc < 3; pc++) {
        const uint32_t stg = sb + pc * STG_M;
        const int kof = pc * 64;
#pragma unroll
        for (int i = 0; i < 2; i++) CPA(stg + sAOff + i * 16, Af + gAOff + kof + i * 8);
#pragma unroll
        for (int i = 0; i < 4; i++) CPA(stg + sBOff + i * 16, Bf + gBOff + kof + i * 8);
        CPA_COMMIT();
    }

    int stage = 0;
    for (int ck = 0; ck < NC; ck++) {
        if (ck + 3 < NC) {
            const uint32_t stg = sb + ((stage + 3) & 3) * STG_M;
            const int kof = (ck + 3) * 64;
#pragma unroll
            for (int i = 0; i < 2; i++) CPA(stg + sAOff + i * 16, Af + gAOff + kof + i * 8);
#pragma unroll
            for (int i = 0; i < 4; i++) CPA(stg + sBOff + i * 16, Bf + gBOff + kof + i * 8);
            CPA_COMMIT();
            CPA_WAIT3();
        } else if (ck + 2 < NC) {
            CPA_WAIT2();
        } else if (ck + 1 < NC) {
            CPA_WAIT1();
        } else {
            CPA_WAIT0();
        }
        __syncthreads();

        const uint32_t pA = sb + stage * STG_M + aOff;
        const uint32_t pB = sb + stage * STG_M + bOff;

        uint32_t A[2][4][4], Bq[2][2][4];
#pragma unroll
        for (int m = 0; m < 4; m++) ldsm4(A[0][m], pA + m * (16 * SRB));
#pragma unroll
        for (int nb = 0; nb < 2; nb++) ldsm4(Bq[0][nb], pB + nb * (16 * SRB));
#pragma unroll
        for (int ka = 0; ka < 4; ka++) {
            const int cur = ka & 1, nxt = cur ^ 1;
            if (ka < 3) {
                const uint32_t ko = (ka + 1) * 32;
#pragma unroll
                for (int m = 0; m < 4; m++) ldsm4(A[nxt][m], pA + m * (16 * SRB) + ko);
#pragma unroll
                for (int nb = 0; nb < 2; nb++) ldsm4(Bq[nxt][nb], pB + nb * (16 * SRB) + ko);
            }
#pragma unroll
            for (int m = 0; m < 4; m++)
#pragma unroll
                for (int n8 = 0; n8 < 4; n8++)
                    mma_fp16(acc[m][n8], A[cur][m],
                             Bq[cur][n8 >> 1][(n8 & 1) * 2], Bq[cur][n8 >> 1][(n8 & 1) * 2 + 1]);
        }
        __syncthreads();
        stage = (stage + 1) & 3;
    }

    // ------------------------------ epilogue --------------------------------
    const int rBase = wm * 64 + (lane >> 2);
    const int cBase = wn * 32 + (lane & 3) * 2;
    if (OM == 0) {
        size_t rowB = ((size_t)bz * BB * SS + (size_t)by * 128) * HH;
#pragma unroll
        for (int m = 0; m < 4; m++) {
            int r0 = m * 16 + rBase;
#pragma unroll
            for (int n8 = 0; n8 < 4; n8++) {
                int cc = bx * 256 + cBase + n8 * 8;
                *(uint32_t*)&g_Tf[rowB + (size_t)r0 * HH + cc] = packh(acc[m][n8][0], acc[m][n8][1]);
                *(uint32_t*)&g_Tf[rowB + (size_t)(r0 + 8) * HH + cc] = packh(acc[m][n8][2], acc[m][n8][3]);
            }
        }
    } else {
        const float* vsp = g_vsum + ((size_t)c * BB + b) * SS + bx * 256;
        float* ob = out + ((size_t)b * CC + c) * SF * SS;
#pragma unroll
        for (int m = 0; m < 4; m++) {
            int r0 = by * 128 + m * 16 + rBase;
#pragma unroll
            for (int n8 = 0; n8 < 4; n8++) {
                int cc = cBase + n8 * 8;
                float2 vs = *(const float2*)(vsp + cc);
                size_t col = (size_t)bx * 256 + cc;
                if (r0 < SF) {
                    float2 o;
                    o.x = acc[m][n8][0] * vs.x;
                    o.y = acc[m][n8][1] * vs.y;
                    *(float2*)(ob + (size_t)r0 * SS + col) = o;
                }
                if (r0 + 8 < SF) {
                    float2 o;
                    o.x = acc[m][n8][2] * vs.x;
                    o.y = acc[m][n8][3] * vs.y;
                    *(float2*)(ob + (size_t)(r0 + 8) * SS + col) = o;
                }
            }
        }
    }
}

// ------------------------------ launch ------------------------------------
extern "C" void kernel_launch(void* const* d_in, const int* in_sizes, int n_in,
                              void* d_out, int out_size) {
    const float* hidden = (const float*)d_in[0];
    const float* emb    = (const float*)d_in[1];
    const float* Wk     = (const float*)d_in[2];
    const float* Wq     = (const float*)d_in[3];
    const float* Wv     = (const float*)d_in[4];
    float* out = (float*)d_out;

    cudaFuncSetAttribute(k_gemm<0>, cudaFuncAttributeMaxDynamicSharedMemorySize, SMEM_G);
    cudaFuncSetAttribute(k_gemm<1>, cudaFuncAttributeMaxDynamicSharedMemorySize, SMEM_G);
    cudaFuncSetAttribute(k_fp16<0>, cudaFuncAttributeMaxDynamicSharedMemorySize, SMEM_M);
    cudaFuncSetAttribute(k_fp16<1>, cudaFuncAttributeMaxDynamicSharedMemorySize, SMEM_M);

    // launch order chosen so the 4th launch (ncu capture slot) is k_fp16<0> (T)
    k_cvt<<<HID_BLOCKS + 64, 256>>>(hidden, emb);                  // 1
    k_tsplit_both<<<dim3(32, 32, 2 * CC), dim3(32, 8)>>>(Wq, Wk);  // 2
    k_gemm<0><<<dim3(4, 8, CC), NT, SMEM_G>>>();                   // 3: McT
    k_fp16<0><<<dim3(4, 256, CC), NT, SMEM_M>>>(nullptr);          // 4: T  <- ncu
    k_gemm<1><<<dim3(4, 1, CC), NT, SMEM_G>>>();                   // 5: E
    k_wvsum<<<dim3(HH / 256, CC), 256>>>(Wv);                      // 6
    k_vsum<<<(BB * SS) / 8, 256>>>(hidden);                        // 7
    k_fp16<1><<<dim3(8, 17, CC * BB), NT, SMEM_M>>>(out);          // 8: scores
}